// round 11
// baseline (speedup 1.0000x reference)
#include <cuda_runtime.h>
#include <cuda_fp16.h>
#include <math.h>
#include <stdint.h>

#define NI 128
#define NT 128
#define RR 48
#define LW 64
#define DD 1024
#define MM (NI*RR)   /* 6144 */
#define NN (NT*LW)   /* 8192 */
#define EPSV 1e-8f
#define LAM 20.0f

// ---------------- scratch (static device globals; no allocation) ----------------
__device__ __align__(16) __half g_qn_h[MM*DD];   // hi(l2norm(img_q))
__device__ __align__(16) __half g_qn_l[MM*DD];   // lo residual
__device__ __align__(16) __half g_tk_h[NN*DD];   // hi(masked l2norm(txt_k))
__device__ __align__(16) __half g_tk_l[NN*DD];
__device__ __align__(16) __half g_iv_h[MM*DD];   // hi(img_v)
__device__ __align__(16) __half g_iv_l[MM*DD];
__device__ __align__(16) __half g_tv_h[NN*DD];   // hi(txt_v)
__device__ __align__(16) __half g_tv_l[NN*DD];
__device__ float g_S[50331648];               // 201 MB S = qn . tkn^T   [6144 x 8192]
__device__ float g_C[50331648];               // 201 MB C = img_v . txt_v^T
__device__ float g_G[NT*LW*LW];               // per-text Gram of txt_v
__device__ float g_H[NI*RR*RR];               // per-image Gram of img_v
__device__ float g_niv[MM];                   // |img_v[n,r]|
__device__ float g_ntv[NN];                   // |txt_v[t,l]|

// ---------------- warp helpers ----------------
__device__ __forceinline__ float wsum(float v){
#pragma unroll
    for (int o = 16; o; o >>= 1) v += __shfl_xor_sync(0xffffffffu, v, o);
    return v;
}
__device__ __forceinline__ float wmax(float v){
#pragma unroll
    for (int o = 16; o; o >>= 1) v = fmaxf(v, __shfl_xor_sync(0xffffffffu, v, o));
    return v;
}
__device__ __forceinline__ uint32_t smem_u32(const void* p){
    uint32_t a;
    asm("{ .reg .u64 t; cvta.to.shared.u64 t, %1; cvt.u32.u64 %0, t; }" : "=r"(a) : "l"(p));
    return a;
}
__device__ __forceinline__ uint32_t h2u(__half2 h){ return *reinterpret_cast<uint32_t*>(&h); }

// split float2 -> (hi half2, lo half2)
__device__ __forceinline__ void f2_split(float x, float y, uint32_t& hi, uint32_t& lo){
    __half2 h = __floats2half2_rn(x, y);
    float2 f = __half22float2(h);
    __half2 l = __floats2half2_rn(x - f.x, y - f.y);
    hi = h2u(h); lo = h2u(l);
}

// ---------------- prep: normalize img_q rows -> halves; split img_v; norms -----------
__global__ void prep_img_kernel(const float* __restrict__ q, const float* __restrict__ v){
    int row = blockIdx.x, tid = threadIdx.x;
    const float4* q4 = (const float4*)(q + (size_t)row * DD);
    const float4* v4 = (const float4*)(v + (size_t)row * DD);
    float4 a = q4[tid], b = v4[tid];
    float sq = a.x*a.x + a.y*a.y + a.z*a.z + a.w*a.w;
    float sv = b.x*b.x + b.y*b.y + b.z*b.z + b.w*b.w;
    __shared__ float s1[8], s2[8];
    sq = wsum(sq); sv = wsum(sv);
    int w = tid >> 5, ln = tid & 31;
    if (ln == 0){ s1[w] = sq; s2[w] = sv; }
    __syncthreads();
    if (tid == 0){
        float t1 = 0.f, t2 = 0.f;
        for (int i = 0; i < 8; i++){ t1 += s1[i]; t2 += s2[i]; }
        s1[0] = t1;
        g_niv[row] = sqrtf(t2);
    }
    __syncthreads();
    float inv = 1.0f / (sqrtf(s1[0]) + EPSV);
    size_t off = (size_t)row * DD + tid * 4;
    uint32_t h0,h1,l0,l1;
    f2_split(a.x*inv, a.y*inv, h0, l0);
    f2_split(a.z*inv, a.w*inv, h1, l1);
    *(uint2*)(g_qn_h + off) = make_uint2(h0, h1);
    *(uint2*)(g_qn_l + off) = make_uint2(l0, l1);
    f2_split(b.x, b.y, h0, l0);
    f2_split(b.z, b.w, h1, l1);
    *(uint2*)(g_iv_h + off) = make_uint2(h0, h1);
    *(uint2*)(g_iv_l + off) = make_uint2(l0, l1);
}

// ---------------- prep: masked-normalize txt_k -> halves; split txt_v; norms ---------
__global__ void prep_txt_kernel(const float* __restrict__ k, const float* __restrict__ v,
                                const int* __restrict__ tlen){
    int row = blockIdx.x, tid = threadIdx.x;
    int t = row >> 6, l = row & 63;
    int len = tlen[t];
    const float4* k4 = (const float4*)(k + (size_t)row * DD);
    const float4* v4 = (const float4*)(v + (size_t)row * DD);
    float4 a = k4[tid], b = v4[tid];
    float sk = a.x*a.x + a.y*a.y + a.z*a.z + a.w*a.w;
    float sv = b.x*b.x + b.y*b.y + b.z*b.z + b.w*b.w;
    __shared__ float s1[8], s2[8];
    sk = wsum(sk); sv = wsum(sv);
    int w = tid >> 5, ln = tid & 31;
    if (ln == 0){ s1[w] = sk; s2[w] = sv; }
    __syncthreads();
    if (tid == 0){
        float t1 = 0.f, t2 = 0.f;
        for (int i = 0; i < 8; i++){ t1 += s1[i]; t2 += s2[i]; }
        s1[0] = t1;
        g_ntv[row] = sqrtf(t2);
    }
    __syncthreads();
    float inv = (l < len) ? (1.0f / (sqrtf(s1[0]) + EPSV)) : 0.0f;
    size_t off = (size_t)row * DD + tid * 4;
    uint32_t h0,h1,l0,l1;
    f2_split(a.x*inv, a.y*inv, h0, l0);
    f2_split(a.z*inv, a.w*inv, h1, l1);
    *(uint2*)(g_tk_h + off) = make_uint2(h0, h1);
    *(uint2*)(g_tk_l + off) = make_uint2(l0, l1);
    f2_split(b.x, b.y, h0, l0);
    f2_split(b.z, b.w, h1, l1);
    *(uint2*)(g_tv_h + off) = make_uint2(h0, h1);
    *(uint2*)(g_tv_l + off) = make_uint2(l0, l1);
}

// ---------------- per-batch Gram: out[b] = X[b] X[b]^T, X[b] is [Rn,1024] ----------------
template<int Rn>
__global__ void gram_kernel(const float* __restrict__ X, float* __restrict__ out){
    __shared__ float sX[64][65];
    int b = blockIdx.x, tid = threadIdx.x;
    int tx = tid & 15, ty = tid >> 4;
    const float* Xb = X + (size_t)b * Rn * DD;
    int i0 = ty * 4, j0 = tx * 4;
    bool act = (i0 < Rn) && (j0 < Rn);
    float acc[4][4];
#pragma unroll
    for (int i = 0; i < 4; i++)
#pragma unroll
        for (int j = 0; j < 4; j++) acc[i][j] = 0.f;
    const int nld = Rn * 16;
    for (int kc = 0; kc < DD; kc += 64){
        for (int idx = tid; idx < nld; idx += 256){
            int r = idx >> 4, kq = idx & 15;
            float4 val = *(const float4*)(Xb + (size_t)r * DD + kc + kq * 4);
            sX[r][kq*4+0] = val.x; sX[r][kq*4+1] = val.y;
            sX[r][kq*4+2] = val.z; sX[r][kq*4+3] = val.w;
        }
        __syncthreads();
        if (act){
#pragma unroll 8
            for (int k = 0; k < 64; k++){
                float ai0 = sX[i0+0][k], ai1 = sX[i0+1][k], ai2 = sX[i0+2][k], ai3 = sX[i0+3][k];
                float bj0 = sX[j0+0][k], bj1 = sX[j0+1][k], bj2 = sX[j0+2][k], bj3 = sX[j0+3][k];
                acc[0][0] += ai0*bj0; acc[0][1] += ai0*bj1; acc[0][2] += ai0*bj2; acc[0][3] += ai0*bj3;
                acc[1][0] += ai1*bj0; acc[1][1] += ai1*bj1; acc[1][2] += ai1*bj2; acc[1][3] += ai1*bj3;
                acc[2][0] += ai2*bj0; acc[2][1] += ai2*bj1; acc[2][2] += ai2*bj2; acc[2][3] += ai2*bj3;
                acc[3][0] += ai3*bj0; acc[3][1] += ai3*bj1; acc[3][2] += ai3*bj2; acc[3][3] += ai3*bj3;
            }
        }
        __syncthreads();
    }
    if (act){
        float* ob = out + (size_t)b * Rn * Rn;
#pragma unroll
        for (int a = 0; a < 4; a++)
#pragma unroll
            for (int c = 0; c < 4; c++)
                ob[(i0+a)*Rn + j0 + c] = acc[a][c];
    }
}

// ---------------- fp16x3 GEMM, pre-split inputs, cp.async + ldmatrix ----------------
// blockIdx.z selects problem: 0 -> S = qn.tkn^T, 1 -> C = img_v.txt_v^T.
// CTA tile 128x128, K-chunk 32, 8 warps x 32x64.

#define KP2 40                      /* halves per smem row (80 B), conflict-free */
#define PLB (128*KP2*2)             /* plane bytes = 10240 */
#define STB (4*PLB)                 /* stage bytes = 40960 (Ah,Al,Bh,Bl) */
#define GEMM_SMEM (2*STB)           /* 81920 double-buffered */
#define NCHUNK 32                   /* 1024 / 32 */

#define MMA_F16(d, a0,a1,a2,a3, b0,b1) \
    asm volatile("mma.sync.aligned.m16n8k16.row.col.f32.f16.f16.f32 " \
        "{%0,%1,%2,%3}, {%4,%5,%6,%7}, {%8,%9}, {%0,%1,%2,%3};" \
        : "+f"(d[0]), "+f"(d[1]), "+f"(d[2]), "+f"(d[3]) \
        : "r"(a0), "r"(a1), "r"(a2), "r"(a3), "r"(b0), "r"(b1))

#define LDSM4(r0,r1,r2,r3, a) \
    asm volatile("ldmatrix.sync.aligned.m8n8.x4.shared.b16 {%0,%1,%2,%3}, [%4];" \
        : "=r"(r0), "=r"(r1), "=r"(r2), "=r"(r3) : "r"(a))

__global__ __launch_bounds__(256)
void gemm_half(const __half* __restrict__ Ah0, const __half* __restrict__ Al0,
               const __half* __restrict__ Bh0, const __half* __restrict__ Bl0,
               float* __restrict__ C0,
               const __half* __restrict__ Ah1, const __half* __restrict__ Al1,
               const __half* __restrict__ Bh1, const __half* __restrict__ Bl1,
               float* __restrict__ C1){
    extern __shared__ __half smh[];
    uint32_t sb = smem_u32(smh);
    int tid = threadIdx.x, lane = tid & 31, warp = tid >> 5;
    int warpM = warp >> 1, warpN = warp & 1;
    int gid = lane >> 2, tig = lane & 3;
    int z = blockIdx.z;
    const __half* Ah = z ? Ah1 : Ah0;
    const __half* Al = z ? Al1 : Al0;
    const __half* Bh = z ? Bh1 : Bh0;
    const __half* Bl = z ? Bl1 : Bl0;
    float* Cg = z ? C1 : C0;

    // staging: plane per 64-thread group (warp-uniform)
    int p = tid >> 6;
    int t64 = tid & 63;
    const __half* pbase = (p == 0) ? Ah : (p == 1) ? Al : (p == 2) ? Bh : Bl;
    int rbase = ((p < 2) ? blockIdx.y : blockIdx.x) * 128;
    const __half* srow0 = pbase + (size_t)rbase * DD;
    uint32_t dplane = p * PLB;

    // ldmatrix per-lane byte offsets within a plane
    // A tiles: T0 rows0-7@k0, T1 rows8-15@k0, T2 rows0-7@k8, T3 rows8-15@k8
    uint32_t aOff = (uint32_t)((warpM*32 + (lane & 15)) * 80 + ((lane & 16) ? 16 : 0));
    // B tiles: T0 n0-7@k0, T1 n0-7@k8, T2 n8-15@k0, T3 n8-15@k8
    uint32_t bOff = (uint32_t)((warpN*64 + ((lane & 7) + ((lane & 16) >> 1))) * 80
                               + ((lane & 8) ? 16 : 0));

    float acc[2][8][4];
#pragma unroll
    for (int mt = 0; mt < 2; mt++)
#pragma unroll
        for (int nt = 0; nt < 8; nt++)
#pragma unroll
            for (int i = 0; i < 4; i++) acc[mt][nt][i] = 0.f;

    auto stage = [&](int c, int st){
        uint32_t dstp = sb + st * STB + dplane;
        const __half* src = srow0 + c * 32;
#pragma unroll
        for (int v = 0; v < 8; v++){
            int o = t64 + v * 64;
            int r = o >> 2, kg = o & 3;
            uint32_t dst = dstp + r * 80 + kg * 16;
            const __half* s = src + (size_t)r * DD + kg * 8;
            asm volatile("cp.async.cg.shared.global [%0], [%1], 16;" :: "r"(dst), "l"(s));
        }
        asm volatile("cp.async.commit_group;" ::: "memory");
    };

    stage(0, 0);
    stage(1, 1);

    for (int c = 0; c < NCHUNK; c++){
        int st = c & 1;
        if (c + 1 < NCHUNK) asm volatile("cp.async.wait_group 1;" ::: "memory");
        else                asm volatile("cp.async.wait_group 0;" ::: "memory");
        __syncthreads();

        uint32_t tb  = sb + st * STB;
        uint32_t tAh = tb + aOff;
        uint32_t tAl = tb + PLB + aOff;
        uint32_t tBh = tb + 2*PLB + bOff;
        uint32_t tBl = tb + 3*PLB + bOff;

#pragma unroll
        for (int ks = 0; ks < 2; ks++){
            uint32_t ko = ks * 32;   // 16 halves
            uint32_t ah[2][4], al[2][4];
            LDSM4(ah[0][0], ah[0][1], ah[0][2], ah[0][3], tAh + ko);
            LDSM4(ah[1][0], ah[1][1], ah[1][2], ah[1][3], tAh + 1280 + ko);
            LDSM4(al[0][0], al[0][1], al[0][2], al[0][3], tAl + ko);
            LDSM4(al[1][0], al[1][1], al[1][2], al[1][3], tAl + 1280 + ko);
#pragma unroll
            for (int np = 0; np < 4; np++){
                uint32_t bh0,bh1,bh2,bh3, bl0,bl1,bl2,bl3;
                LDSM4(bh0,bh1,bh2,bh3, tBh + np*1280 + ko);
                LDSM4(bl0,bl1,bl2,bl3, tBl + np*1280 + ko);
#pragma unroll
                for (int mt = 0; mt < 2; mt++){
                    MMA_F16(acc[mt][2*np],   ah[mt][0],ah[mt][1],ah[mt][2],ah[mt][3], bh0, bh1);
                    MMA_F16(acc[mt][2*np],   ah[mt][0],ah[mt][1],ah[mt][2],ah[mt][3], bl0, bl1);
                    MMA_F16(acc[mt][2*np],   al[mt][0],al[mt][1],al[mt][2],al[mt][3], bh0, bh1);
                    MMA_F16(acc[mt][2*np+1], ah[mt][0],ah[mt][1],ah[mt][2],ah[mt][3], bh2, bh3);
                    MMA_F16(acc[mt][2*np+1], ah[mt][0],ah[mt][1],ah[mt][2],ah[mt][3], bl2, bl3);
                    MMA_F16(acc[mt][2*np+1], al[mt][0],al[mt][1],al[mt][2],al[mt][3], bh2, bh3);
                }
            }
        }
        __syncthreads();
        if (c + 2 < NCHUNK) stage(c + 2, st);
    }

    // write back (same fragment mapping as before)
    int mBase = blockIdx.y*128 + warpM*32;
    int nBase = blockIdx.x*128 + warpN*64;
#pragma unroll
    for (int mt = 0; mt < 2; mt++)
#pragma unroll
        for (int nt = 0; nt < 8; nt++){
            int m0 = mBase + mt*16 + gid;
            int n0 = nBase + nt*8 + tig*2;
            float2 v0 = {acc[mt][nt][0], acc[mt][nt][1]};
            float2 v1 = {acc[mt][nt][2], acc[mt][nt][3]};
            *(float2*)(Cg + (size_t)m0 * NN + n0) = v0;
            *(float2*)(Cg + (size_t)(m0+8) * NN + n0) = v1;
        }
}

// ---------------- epilogue: per (n,t) pair attention + focal + cosine ----------------
__global__ void epilogue_kernel(const int* __restrict__ tlen, float* __restrict__ out){
    __shared__ float sS[RR*65];
    __shared__ float sCt[LW*49];
    __shared__ float sGH[LW*65];
    __shared__ float colnorm[LW];
    __shared__ float rownorm[RR];
    __shared__ float wacc[8];

    int n = blockIdx.y, t = blockIdx.x;
    int tid = threadIdx.x, warp = tid >> 5, lane = tid & 31;
    int len = tlen[t];
    float lenf = (float)len;

    for (int idx = tid; idx < RR*16; idx += 256){
        int r = idx >> 4, q = idx & 15;
        float4 v = *(const float4*)(g_S + (size_t)(n*RR + r) * NN + t*LW + q*4);
        float* d = &sS[r*65 + q*4];
        d[0] = v.x >= 0.f ? v.x : 0.1f*v.x;
        d[1] = v.y >= 0.f ? v.y : 0.1f*v.y;
        d[2] = v.z >= 0.f ? v.z : 0.1f*v.z;
        d[3] = v.w >= 0.f ? v.w : 0.1f*v.w;
    }
    for (int idx = tid; idx < RR*16; idx += 256){
        int r = idx >> 4, q = idx & 15;
        float4 v = *(const float4*)(g_C + (size_t)(n*RR + r) * NN + t*LW + q*4);
        sCt[(q*4+0)*49 + r] = v.x; sCt[(q*4+1)*49 + r] = v.y;
        sCt[(q*4+2)*49 + r] = v.z; sCt[(q*4+3)*49 + r] = v.w;
    }
    for (int idx = tid; idx < LW*16; idx += 256){
        int l = idx >> 4, q = idx & 15;
        float4 v = *(const float4*)(g_G + (size_t)t*LW*LW + l*LW + q*4);
        float* d = &sGH[l*65 + q*4];
        d[0] = v.x; d[1] = v.y; d[2] = v.z; d[3] = v.w;
    }
    __syncthreads();

    if (tid < LW){
        float s = 0.f;
        for (int r = 0; r < RR; r++){ float v = sS[r*65 + tid]; s += v*v; }
        colnorm[tid] = sqrtf(s) + EPSV;
    } else if (tid < LW + RR){
        int r = tid - LW; float s = 0.f;
        for (int l = 0; l < LW; l++){ float v = sS[r*65 + l]; s += v*v; }
        rownorm[r] = sqrtf(s) + EPSV;
    }
    __syncthreads();

    // ---- i2t ----
    float accI = 0.f;
    for (int r = warp; r < RR; r += 8){
        int l0 = lane, l1 = lane + 32;
        bool m0 = l0 < len, m1 = l1 < len;
        float x0 = m0 ? sS[r*65 + l0] / colnorm[l0] * LAM : -1e30f;
        float x1 = m1 ? sS[r*65 + l1] / colnorm[l1] * LAM : -1e30f;
        float mx = wmax(fmaxf(x0, x1));
        float e0 = m0 ? expf(x0 - mx) : 0.f;
        float e1 = m1 ? expf(x1 - mx) : 0.f;
        float sE = wsum(e0 + e1);
        float a0 = e0 / sE, a1 = e1 / sE;
        float sA = wsum(a0 + a1);
        float ta0 = (a0 * lenf - sA > 0.f) ? a0 : 0.f;
        float ta1 = (a1 * lenf - sA > 0.f) ? a1 : 0.f;
        float sT = wsum(ta0 + ta1);
        float dn = sT > 0.f ? sT : 1.f;
        float f0 = ta0 / dn, f1 = ta1 / dn;
        float num = wsum(f0 * sCt[l0*49 + r] + f1 * sCt[l1*49 + r]);
        float qd = 0.f;
        for (int lp = 0; lp < LW; lp++){
            float alp = (lp < 32) ? __shfl_sync(0xffffffffu, f0, lp)
                                  : __shfl_sync(0xffffffffu, f1, lp - 32);
            qd += alp * (f0 * sGH[l0*65 + lp] + f1 * sGH[l1*65 + lp]);
        }
        qd = wsum(qd);
        float wn = sqrtf(fmaxf(qd, 0.f));
        float inv = 1.f / (wn + EPSV);
        float xw = num * inv, whn = wn * inv;
        float den = fmaxf(g_niv[n*RR + r] * whn, EPSV);
        accI += xw / den;
    }
    if (lane == 0) wacc[warp] = accI;
    __syncthreads();
    if (tid == 0){
        float s = 0.f;
        for (int i = 0; i < 8; i++) s += wacc[i];
        out[n*NT + t] = s / (float)RR;
    }
    __syncthreads();

    for (int idx = tid; idx < RR*RR; idx += 256){
        int r = idx / RR, c = idx - r*RR;
        sGH[r*49 + c] = g_H[(size_t)n*RR*RR + idx];
    }
    __syncthreads();

    // ---- t2i ----
    float accT = 0.f;
    for (int l = warp; l < LW; l += 8){
        int r0 = lane;
        bool h1 = lane < 16;
        int r1 = lane + 32;
        float y0 = sS[r0*65 + l] / rownorm[r0] * LAM;
        float y1 = h1 ? sS[r1*65 + l] / rownorm[r1] * LAM : -1e30f;
        float mx = wmax(fmaxf(y0, y1));
        float e0 = expf(y0 - mx);
        float e1 = h1 ? expf(y1 - mx) : 0.f;
        float sE = wsum(e0 + e1);
        float a0 = e0 / sE, a1 = e1 / sE;
        float sA = wsum(a0 + a1);
        float ta0 = (a0 * (float)RR - sA > 0.f) ? a0 : 0.f;
        float ta1 = (a1 * (float)RR - sA > 0.f) ? a1 : 0.f;
        float sT = wsum(ta0 + ta1);
        float dn = sT > 0.f ? sT : 1.f;
        float f0 = ta0 / dn, f1 = ta1 / dn;
        float num = f0 * sCt[l*49 + r0] + (h1 ? f1 * sCt[l*49 + r1] : 0.f);
        num = wsum(num);
        float qd = 0.f;
        for (int rp = 0; rp < RR; rp++){
            float arp = (rp < 32) ? __shfl_sync(0xffffffffu, f0, rp)
                                  : __shfl_sync(0xffffffffu, f1, rp - 32);
            float term = f0 * sGH[r0*49 + rp];
            if (h1) term += f1 * sGH[r1*49 + rp];
            qd += arp * term;
        }
        qd = wsum(qd);
        float wn = sqrtf(fmaxf(qd, 0.f));
        float inv = 1.f / (wn + EPSV);
        float xw = num * inv, whn = wn * inv;
        float den = fmaxf(g_ntv[t*LW + l] * whn, EPSV);
        float c2 = xw / den;
        if (l < len) accT += c2;
    }
    if (lane == 0) wacc[warp] = accT;
    __syncthreads();
    if (tid == 0){
        float s = 0.f;
        for (int i = 0; i < 8; i++) s += wacc[i];
        out[NI*NT + n*NT + t] = s / lenf;
    }
}

// ---------------- launch ----------------
extern "C" void kernel_launch(void* const* d_in, const int* in_sizes, int n_in,
                              void* d_out, int out_size){
    (void)in_sizes; (void)n_in; (void)out_size;
    const float* img_q = (const float*)d_in[0];
    const float* img_v = (const float*)d_in[1];
    const float* txt_k = (const float*)d_in[2];
    const float* txt_v = (const float*)d_in[3];
    const int*   tlen  = (const int*)d_in[4];
    float* out = (float*)d_out;

    void *pS, *pC, *pG, *pH;
    void *pqh, *pql, *pkh, *pkl, *pih, *pil, *pvh, *pvl;
    cudaGetSymbolAddress(&pS, g_S);
    cudaGetSymbolAddress(&pC, g_C);
    cudaGetSymbolAddress(&pG, g_G);
    cudaGetSymbolAddress(&pH, g_H);
    cudaGetSymbolAddress(&pqh, g_qn_h);
    cudaGetSymbolAddress(&pql, g_qn_l);
    cudaGetSymbolAddress(&pkh, g_tk_h);
    cudaGetSymbolAddress(&pkl, g_tk_l);
    cudaGetSymbolAddress(&pih, g_iv_h);
    cudaGetSymbolAddress(&pil, g_iv_l);
    cudaGetSymbolAddress(&pvh, g_tv_h);
    cudaGetSymbolAddress(&pvl, g_tv_l);

    cudaFuncSetAttribute(gemm_half, cudaFuncAttributeMaxDynamicSharedMemorySize, GEMM_SMEM);

    prep_img_kernel<<<MM, 256>>>(img_q, img_v);
    prep_txt_kernel<<<NN, 256>>>(txt_k, txt_v, tlen);
    gram_kernel<RR><<<NI, 256>>>(img_v, (float*)pH);
    gram_kernel<LW><<<NT, 256>>>(txt_v, (float*)pG);

    dim3 gg(NN/128, MM/128, 2);   // 64 x 48 x 2 (z: 0 -> S, 1 -> C)
    gemm_half<<<gg, 256, GEMM_SMEM>>>(
        (const __half*)pqh, (const __half*)pql, (const __half*)pkh, (const __half*)pkl, (float*)pS,
        (const __half*)pih, (const __half*)pil, (const __half*)pvh, (const __half*)pvl, (float*)pC);

    dim3 ge(NT, NI);           // x = t, y = n
    epilogue_kernel<<<ge, 256>>>(tlen, out);
}

// round 13
// speedup vs baseline: 1.2062x; 1.2062x over previous
#include <cuda_runtime.h>
#include <cuda_fp16.h>
#include <math.h>
#include <stdint.h>

#define NI 128
#define NT 128
#define RR 48
#define LW 64
#define DD 1024
#define MM (NI*RR)   /* 6144 */
#define NN (NT*LW)   /* 8192 */
#define EPSV 1e-8f
#define LAM 20.0f

// ---------------- scratch (static device globals; no allocation) ----------------
__device__ __align__(16) __half g_qn_h[MM*DD];   // hi(l2norm(img_q))
__device__ __align__(16) __half g_qn_l[MM*DD];   // lo residual
__device__ __align__(16) __half g_tk_h[NN*DD];   // hi(masked l2norm(txt_k))
__device__ __align__(16) __half g_tk_l[NN*DD];
__device__ __align__(16) __half g_iv_h[MM*DD];   // fp16(img_v)  (1-term C path)
__device__ __align__(16) __half g_tv_h[NN*DD];   // fp16(txt_v)
__device__ float g_S[50331648];               // 201 MB S = qn . tkn^T   [6144 x 8192]
__device__ float g_C[50331648];               // 201 MB C = img_v . txt_v^T
__device__ float g_G[NT*LW*LW];               // per-text Gram of txt_v
__device__ float g_H[NI*RR*RR];               // per-image Gram of img_v
__device__ float g_niv[MM];                   // |img_v[n,r]|
__device__ float g_ntv[NN];                   // |txt_v[t,l]|

// ---------------- warp helpers ----------------
__device__ __forceinline__ float wsum(float v){
#pragma unroll
    for (int o = 16; o; o >>= 1) v += __shfl_xor_sync(0xffffffffu, v, o);
    return v;
}
__device__ __forceinline__ float wmax(float v){
#pragma unroll
    for (int o = 16; o; o >>= 1) v = fmaxf(v, __shfl_xor_sync(0xffffffffu, v, o));
    return v;
}
__device__ __forceinline__ uint32_t smem_u32(const void* p){
    uint32_t a;
    asm("{ .reg .u64 t; cvta.to.shared.u64 t, %1; cvt.u32.u64 %0, t; }" : "=r"(a) : "l"(p));
    return a;
}
__device__ __forceinline__ uint32_t h2u(__half2 h){ return *reinterpret_cast<uint32_t*>(&h); }

// split float2 -> (hi half2, lo half2)
__device__ __forceinline__ void f2_split(float x, float y, uint32_t& hi, uint32_t& lo){
    __half2 h = __floats2half2_rn(x, y);
    float2 f = __half22float2(h);
    __half2 l = __floats2half2_rn(x - f.x, y - f.y);
    hi = h2u(h); lo = h2u(l);
}

// ---------------- prep: normalize img_q rows -> hi/lo halves; fp16 img_v; norms -----
__global__ void prep_img_kernel(const float* __restrict__ q, const float* __restrict__ v){
    int row = blockIdx.x, tid = threadIdx.x;
    const float4* q4 = (const float4*)(q + (size_t)row * DD);
    const float4* v4 = (const float4*)(v + (size_t)row * DD);
    float4 a = q4[tid], b = v4[tid];
    float sq = a.x*a.x + a.y*a.y + a.z*a.z + a.w*a.w;
    float sv = b.x*b.x + b.y*b.y + b.z*b.z + b.w*b.w;
    __shared__ float s1[8], s2[8];
    sq = wsum(sq); sv = wsum(sv);
    int w = tid >> 5, ln = tid & 31;
    if (ln == 0){ s1[w] = sq; s2[w] = sv; }
    __syncthreads();
    if (tid == 0){
        float t1 = 0.f, t2 = 0.f;
        for (int i = 0; i < 8; i++){ t1 += s1[i]; t2 += s2[i]; }
        s1[0] = t1;
        g_niv[row] = sqrtf(t2);
    }
    __syncthreads();
    float inv = 1.0f / (sqrtf(s1[0]) + EPSV);
    size_t off = (size_t)row * DD + tid * 4;
    uint32_t h0,h1,l0,l1;
    f2_split(a.x*inv, a.y*inv, h0, l0);
    f2_split(a.z*inv, a.w*inv, h1, l1);
    *(uint2*)(g_qn_h + off) = make_uint2(h0, h1);
    *(uint2*)(g_qn_l + off) = make_uint2(l0, l1);
    __half2 vh0 = __floats2half2_rn(b.x, b.y);
    __half2 vh1 = __floats2half2_rn(b.z, b.w);
    *(uint2*)(g_iv_h + off) = make_uint2(h2u(vh0), h2u(vh1));
}

// ---------------- prep: masked-normalize txt_k -> hi/lo; fp16 txt_v; norms ----------
__global__ void prep_txt_kernel(const float* __restrict__ k, const float* __restrict__ v,
                                const int* __restrict__ tlen){
    int row = blockIdx.x, tid = threadIdx.x;
    int t = row >> 6, l = row & 63;
    int len = tlen[t];
    const float4* k4 = (const float4*)(k + (size_t)row * DD);
    const float4* v4 = (const float4*)(v + (size_t)row * DD);
    float4 a = k4[tid], b = v4[tid];
    float sk = a.x*a.x + a.y*a.y + a.z*a.z + a.w*a.w;
    float sv = b.x*b.x + b.y*b.y + b.z*b.z + b.w*b.w;
    __shared__ float s1[8], s2[8];
    sk = wsum(sk); sv = wsum(sv);
    int w = tid >> 5, ln = tid & 31;
    if (ln == 0){ s1[w] = sk; s2[w] = sv; }
    __syncthreads();
    if (tid == 0){
        float t1 = 0.f, t2 = 0.f;
        for (int i = 0; i < 8; i++){ t1 += s1[i]; t2 += s2[i]; }
        s1[0] = t1;
        g_ntv[row] = sqrtf(t2);
    }
    __syncthreads();
    float inv = (l < len) ? (1.0f / (sqrtf(s1[0]) + EPSV)) : 0.0f;
    size_t off = (size_t)row * DD + tid * 4;
    uint32_t h0,h1,l0,l1;
    f2_split(a.x*inv, a.y*inv, h0, l0);
    f2_split(a.z*inv, a.w*inv, h1, l1);
    *(uint2*)(g_tk_h + off) = make_uint2(h0, h1);
    *(uint2*)(g_tk_l + off) = make_uint2(l0, l1);
    __half2 vh0 = __floats2half2_rn(b.x, b.y);
    __half2 vh1 = __floats2half2_rn(b.z, b.w);
    *(uint2*)(g_tv_h + off) = make_uint2(h2u(vh0), h2u(vh1));
}

// ---------------- per-batch Gram: out[b] = X[b] X[b]^T, X[b] is [Rn,1024] ----------------
template<int Rn>
__global__ void gram_kernel(const float* __restrict__ X, float* __restrict__ out){
    __shared__ float sX[64][65];
    int b = blockIdx.x, tid = threadIdx.x;
    int tx = tid & 15, ty = tid >> 4;
    const float* Xb = X + (size_t)b * Rn * DD;
    int i0 = ty * 4, j0 = tx * 4;
    bool act = (i0 < Rn) && (j0 < Rn);
    float acc[4][4];
#pragma unroll
    for (int i = 0; i < 4; i++)
#pragma unroll
        for (int j = 0; j < 4; j++) acc[i][j] = 0.f;
    const int nld = Rn * 16;
    for (int kc = 0; kc < DD; kc += 64){
        for (int idx = tid; idx < nld; idx += 256){
            int r = idx >> 4, kq = idx & 15;
            float4 val = *(const float4*)(Xb + (size_t)r * DD + kc + kq * 4);
            sX[r][kq*4+0] = val.x; sX[r][kq*4+1] = val.y;
            sX[r][kq*4+2] = val.z; sX[r][kq*4+3] = val.w;
        }
        __syncthreads();
        if (act){
#pragma unroll 8
            for (int k = 0; k < 64; k++){
                float ai0 = sX[i0+0][k], ai1 = sX[i0+1][k], ai2 = sX[i0+2][k], ai3 = sX[i0+3][k];
                float bj0 = sX[j0+0][k], bj1 = sX[j0+1][k], bj2 = sX[j0+2][k], bj3 = sX[j0+3][k];
                acc[0][0] += ai0*bj0; acc[0][1] += ai0*bj1; acc[0][2] += ai0*bj2; acc[0][3] += ai0*bj3;
                acc[1][0] += ai1*bj0; acc[1][1] += ai1*bj1; acc[1][2] += ai1*bj2; acc[1][3] += ai1*bj3;
                acc[2][0] += ai2*bj0; acc[2][1] += ai2*bj1; acc[2][2] += ai2*bj2; acc[2][3] += ai2*bj3;
                acc[3][0] += ai3*bj0; acc[3][1] += ai3*bj1; acc[3][2] += ai3*bj2; acc[3][3] += ai3*bj3;
            }
        }
        __syncthreads();
    }
    if (act){
        float* ob = out + (size_t)b * Rn * Rn;
#pragma unroll
        for (int a = 0; a < 4; a++)
#pragma unroll
            for (int c = 0; c < 4; c++)
                ob[(i0+a)*Rn + j0 + c] = acc[a][c];
    }
}

// ---------------- GEMM common: CTA 128x128, K-chunk 32, 8 warps x 32x64 ----------------
#define KP2 40                      /* halves per smem row (80 B), conflict-free */
#define PLB (128*KP2*2)             /* plane bytes = 10240 */
#define NCHUNK 32                   /* 1024 / 32 */
#define STB3 (4*PLB)                /* 3-term stage: Ah,Al,Bh,Bl = 40960 */
#define SMEM3 (2*STB3)              /* 81920 */
#define STB1 (2*PLB)                /* 1-term stage: Ah,Bh = 20480 */
#define SMEM1 (2*STB1)              /* 40960 */

#define MMA_F16(d, a0,a1,a2,a3, b0,b1) \
    asm volatile("mma.sync.aligned.m16n8k16.row.col.f32.f16.f16.f32 " \
        "{%0,%1,%2,%3}, {%4,%5,%6,%7}, {%8,%9}, {%0,%1,%2,%3};" \
        : "+f"(d[0]), "+f"(d[1]), "+f"(d[2]), "+f"(d[3]) \
        : "r"(a0), "r"(a1), "r"(a2), "r"(a3), "r"(b0), "r"(b1))

#define LDSM4(r0,r1,r2,r3, a) \
    asm volatile("ldmatrix.sync.aligned.m8n8.x4.shared.b16 {%0,%1,%2,%3}, [%4];" \
        : "=r"(r0), "=r"(r1), "=r"(r2), "=r"(r3) : "r"(a))

// ---- 3-term compensated GEMM (for S): acc += Ah*Bh + Ah*Bl + Al*Bh ----
__global__ __launch_bounds__(256)
void gemm_f16x3(const __half* __restrict__ Ah, const __half* __restrict__ Al,
                const __half* __restrict__ Bh, const __half* __restrict__ Bl,
                float* __restrict__ Cg){
    extern __shared__ __half smh[];
    uint32_t sb = smem_u32(smh);
    int tid = threadIdx.x, lane = tid & 31, warp = tid >> 5;
    int warpM = warp >> 1, warpN = warp & 1;
    int gid = lane >> 2, tig = lane & 3;

    int p = tid >> 6;
    int t64 = tid & 63;
    const __half* pbase = (p == 0) ? Ah : (p == 1) ? Al : (p == 2) ? Bh : Bl;
    int rbase = ((p < 2) ? blockIdx.y : blockIdx.x) * 128;
    const __half* srow0 = pbase + (size_t)rbase * DD;
    uint32_t dplane = p * PLB;

    uint32_t aOff = (uint32_t)((warpM*32 + (lane & 15)) * 80 + ((lane & 16) ? 16 : 0));
    uint32_t bOff = (uint32_t)((warpN*64 + ((lane & 7) + ((lane & 16) >> 1))) * 80
                               + ((lane & 8) ? 16 : 0));

    float acc[2][8][4];
#pragma unroll
    for (int mt = 0; mt < 2; mt++)
#pragma unroll
        for (int nt = 0; nt < 8; nt++)
#pragma unroll
            for (int i = 0; i < 4; i++) acc[mt][nt][i] = 0.f;

    auto stage = [&](int c, int st){
        uint32_t dstp = sb + st * STB3 + dplane;
        const __half* src = srow0 + c * 32;
#pragma unroll
        for (int v = 0; v < 8; v++){
            int o = t64 + v * 64;
            int r = o >> 2, kg = o & 3;
            uint32_t dst = dstp + r * 80 + kg * 16;
            const __half* s = src + (size_t)r * DD + kg * 8;
            asm volatile("cp.async.cg.shared.global [%0], [%1], 16;" :: "r"(dst), "l"(s));
        }
        asm volatile("cp.async.commit_group;" ::: "memory");
    };

    stage(0, 0);
    stage(1, 1);

    for (int c = 0; c < NCHUNK; c++){
        int st = c & 1;
        if (c + 1 < NCHUNK) asm volatile("cp.async.wait_group 1;" ::: "memory");
        else                asm volatile("cp.async.wait_group 0;" ::: "memory");
        __syncthreads();

        uint32_t tb  = sb + st * STB3;
        uint32_t tAh = tb + aOff;
        uint32_t tAl = tb + PLB + aOff;
        uint32_t tBh = tb + 2*PLB + bOff;
        uint32_t tBl = tb + 3*PLB + bOff;

#pragma unroll
        for (int ks = 0; ks < 2; ks++){
            uint32_t ko = ks * 32;
            uint32_t ah[2][4], al[2][4];
            LDSM4(ah[0][0], ah[0][1], ah[0][2], ah[0][3], tAh + ko);
            LDSM4(ah[1][0], ah[1][1], ah[1][2], ah[1][3], tAh + 1280 + ko);
            LDSM4(al[0][0], al[0][1], al[0][2], al[0][3], tAl + ko);
            LDSM4(al[1][0], al[1][1], al[1][2], al[1][3], tAl + 1280 + ko);
#pragma unroll
            for (int np = 0; np < 4; np++){
                uint32_t bh0,bh1,bh2,bh3, bl0,bl1,bl2,bl3;
                LDSM4(bh0,bh1,bh2,bh3, tBh + np*1280 + ko);
                LDSM4(bl0,bl1,bl2,bl3, tBl + np*1280 + ko);
#pragma unroll
                for (int mt = 0; mt < 2; mt++){
                    MMA_F16(acc[mt][2*np],   ah[mt][0],ah[mt][1],ah[mt][2],ah[mt][3], bh0, bh1);
                    MMA_F16(acc[mt][2*np],   ah[mt][0],ah[mt][1],ah[mt][2],ah[mt][3], bl0, bl1);
                    MMA_F16(acc[mt][2*np],   al[mt][0],al[mt][1],al[mt][2],al[mt][3], bh0, bh1);
                    MMA_F16(acc[mt][2*np+1], ah[mt][0],ah[mt][1],ah[mt][2],ah[mt][3], bh2, bh3);
                    MMA_F16(acc[mt][2*np+1], ah[mt][0],ah[mt][1],ah[mt][2],ah[mt][3], bl2, bl3);
                    MMA_F16(acc[mt][2*np+1], al[mt][0],al[mt][1],al[mt][2],al[mt][3], bh2, bh3);
                }
            }
        }
        __syncthreads();
        if (c + 2 < NCHUNK) stage(c + 2, st);
    }

    int mBase = blockIdx.y*128 + warpM*32;
    int nBase = blockIdx.x*128 + warpN*64;
#pragma unroll
    for (int mt = 0; mt < 2; mt++)
#pragma unroll
        for (int nt = 0; nt < 8; nt++){
            int m0 = mBase + mt*16 + gid;
            int n0 = nBase + nt*8 + tig*2;
            float2 v0 = {acc[mt][nt][0], acc[mt][nt][1]};
            float2 v1 = {acc[mt][nt][2], acc[mt][nt][3]};
            *(float2*)(Cg + (size_t)m0 * NN + n0) = v0;
            *(float2*)(Cg + (size_t)(m0+8) * NN + n0) = v1;
        }
}

// ---- 1-term plain-fp16 GEMM (for C): acc += Ah*Bh ----
__global__ __launch_bounds__(256)
void gemm_f16x1(const __half* __restrict__ Ah, const __half* __restrict__ Bh,
                float* __restrict__ Cg){
    extern __shared__ __half smh[];
    uint32_t sb = smem_u32(smh);
    int tid = threadIdx.x, lane = tid & 31, warp = tid >> 5;
    int warpM = warp >> 1, warpN = warp & 1;
    int gid = lane >> 2, tig = lane & 3;

    int p = tid >> 7;            // 0 -> A plane, 1 -> B plane (128 threads each)
    int t128 = tid & 127;
    const __half* pbase = p ? Bh : Ah;
    int rbase = (p ? blockIdx.x : blockIdx.y) * 128;
    const __half* srow0 = pbase + (size_t)rbase * DD;
    uint32_t dplane = p * PLB;

    uint32_t aOff = (uint32_t)((warpM*32 + (lane & 15)) * 80 + ((lane & 16) ? 16 : 0));
    uint32_t bOff = (uint32_t)((warpN*64 + ((lane & 7) + ((lane & 16) >> 1))) * 80
                               + ((lane & 8) ? 16 : 0));

    float acc[2][8][4];
#pragma unroll
    for (int mt = 0; mt < 2; mt++)
#pragma unroll
        for (int nt = 0; nt < 8; nt++)
#pragma unroll
            for (int i = 0; i < 4; i++) acc[mt][nt][i] = 0.f;

    auto stage = [&](int c, int st){
        uint32_t dstp = sb + st * STB1 + dplane;
        const __half* src = srow0 + c * 32;
#pragma unroll
        for (int v = 0; v < 4; v++){
            int o = t128 + v * 128;
            int r = o >> 2, kg = o & 3;
            uint32_t dst = dstp + r * 80 + kg * 16;
            const __half* s = src + (size_t)r * DD + kg * 8;
            asm volatile("cp.async.cg.shared.global [%0], [%1], 16;" :: "r"(dst), "l"(s));
        }
        asm volatile("cp.async.commit_group;" ::: "memory");
    };

    stage(0, 0);
    stage(1, 1);

    for (int c = 0; c < NCHUNK; c++){
        int st = c & 1;
        if (c + 1 < NCHUNK) asm volatile("cp.async.wait_group 1;" ::: "memory");
        else                asm volatile("cp.async.wait_group 0;" ::: "memory");
        __syncthreads();

        uint32_t tb  = sb + st * STB1;
        uint32_t tAh = tb + aOff;
        uint32_t tBh = tb + PLB + bOff;

#pragma unroll
        for (int ks = 0; ks < 2; ks++){
            uint32_t ko = ks * 32;
            uint32_t ah[2][4];
            LDSM4(ah[0][0], ah[0][1], ah[0][2], ah[0][3], tAh + ko);
            LDSM4(ah[1][0], ah[1][1], ah[1][2], ah[1][3], tAh + 1280 + ko);
#pragma unroll
            for (int np = 0; np < 4; np++){
                uint32_t bh0,bh1,bh2,bh3;
                LDSM4(bh0,bh1,bh2,bh3, tBh + np*1280 + ko);
#pragma unroll
                for (int mt = 0; mt < 2; mt++){
                    MMA_F16(acc[mt][2*np],   ah[mt][0],ah[mt][1],ah[mt][2],ah[mt][3], bh0, bh1);
                    MMA_F16(acc[mt][2*np+1], ah[mt][0],ah[mt][1],ah[mt][2],ah[mt][3], bh2, bh3);
                }
            }
        }
        __syncthreads();
        if (c + 2 < NCHUNK) stage(c + 2, st);
    }

    int mBase = blockIdx.y*128 + warpM*32;
    int nBase = blockIdx.x*128 + warpN*64;
#pragma unroll
    for (int mt = 0; mt < 2; mt++)
#pragma unroll
        for (int nt = 0; nt < 8; nt++){
            int m0 = mBase + mt*16 + gid;
            int n0 = nBase + nt*8 + tig*2;
            float2 v0 = {acc[mt][nt][0], acc[mt][nt][1]};
            float2 v1 = {acc[mt][nt][2], acc[mt][nt][3]};
            *(float2*)(Cg + (size_t)m0 * NN + n0) = v0;
            *(float2*)(Cg + (size_t)(m0+8) * NN + n0) = v1;
        }
}

// ---------------- epilogue: per (n,t) pair attention + focal + cosine ----------------
__global__ void epilogue_kernel(const int* __restrict__ tlen, float* __restrict__ out){
    __shared__ float sS[RR*65];
    __shared__ float sCt[LW*49];
    __shared__ float sGH[LW*65];
    __shared__ float colnorm[LW];
    __shared__ float rownorm[RR];
    __shared__ float wacc[8];

    int n = blockIdx.y, t = blockIdx.x;
    int tid = threadIdx.x, warp = tid >> 5, lane = tid & 31;
    int len = tlen[t];
    float lenf = (float)len;

    for (int idx = tid; idx < RR*16; idx += 256){
        int r = idx >> 4, q = idx & 15;
        float4 v = *(const float4*)(g_S + (size_t)(n*RR + r) * NN + t*LW + q*4);
        float* d = &sS[r*65 + q*4];
        d[0] = v.x >= 0.f ? v.x : 0.1f*v.x;
        d[1] = v.y >= 0.f ? v.y : 0.1f*v.y;
        d[2] = v.z >= 0.f ? v.z : 0.1f*v.z;
        d[3] = v.w >= 0.f ? v.w : 0.1f*v.w;
    }
    for (int idx = tid; idx < RR*16; idx += 256){
        int r = idx >> 4, q = idx & 15;
        float4 v = *(const float4*)(g_C + (size_t)(n*RR + r) * NN + t*LW + q*4);
        sCt[(q*4+0)*49 + r] = v.x; sCt[(q*4+1)*49 + r] = v.y;
        sCt[(q*4+2)*49 + r] = v.z; sCt[(q*4+3)*49 + r] = v.w;
    }
    for (int idx = tid; idx < LW*16; idx += 256){
        int l = idx >> 4, q = idx & 15;
        float4 v = *(const float4*)(g_G + (size_t)t*LW*LW + l*LW + q*4);
        float* d = &sGH[l*65 + q*4];
        d[0] = v.x; d[1] = v.y; d[2] = v.z; d[3] = v.w;
    }
    __syncthreads();

    if (tid < LW){
        float s = 0.f;
        for (int r = 0; r < RR; r++){ float v = sS[r*65 + tid]; s += v*v; }
        colnorm[tid] = sqrtf(s) + EPSV;
    } else if (tid < LW + RR){
        int r = tid - LW; float s = 0.f;
        for (int l = 0; l < LW; l++){ float v = sS[r*65 + l]; s += v*v; }
        rownorm[r] = sqrtf(s) + EPSV;
    }
    __syncthreads();

    // ---- i2t ----
    float accI = 0.f;
    for (int r = warp; r < RR; r += 8){
        int l0 = lane, l1 = lane + 32;
        bool m0 = l0 < len, m1 = l1 < len;
        float x0 = m0 ? sS[r*65 + l0] / colnorm[l0] * LAM : -1e30f;
        float x1 = m1 ? sS[r*65 + l1] / colnorm[l1] * LAM : -1e30f;
        float mx = wmax(fmaxf(x0, x1));
        float e0 = m0 ? expf(x0 - mx) : 0.f;
        float e1 = m1 ? expf(x1 - mx) : 0.f;
        float sE = wsum(e0 + e1);
        float a0 = e0 / sE, a1 = e1 / sE;
        float sA = wsum(a0 + a1);
        float ta0 = (a0 * lenf - sA > 0.f) ? a0 : 0.f;
        float ta1 = (a1 * lenf - sA > 0.f) ? a1 : 0.f;
        float sT = wsum(ta0 + ta1);
        float dn = sT > 0.f ? sT : 1.f;
        float f0 = ta0 / dn, f1 = ta1 / dn;
        float num = wsum(f0 * sCt[l0*49 + r] + f1 * sCt[l1*49 + r]);
        float qd = 0.f;
        for (int lp = 0; lp < LW; lp++){
            float alp = (lp < 32) ? __shfl_sync(0xffffffffu, f0, lp)
                                  : __shfl_sync(0xffffffffu, f1, lp - 32);
            qd += alp * (f0 * sGH[l0*65 + lp] + f1 * sGH[l1*65 + lp]);
        }
        qd = wsum(qd);
        float wn = sqrtf(fmaxf(qd, 0.f));
        float inv = 1.f / (wn + EPSV);
        float xw = num * inv, whn = wn * inv;
        float den = fmaxf(g_niv[n*RR + r] * whn, EPSV);
        accI += xw / den;
    }
    if (lane == 0) wacc[warp] = accI;
    __syncthreads();
    if (tid == 0){
        float s = 0.f;
        for (int i = 0; i < 8; i++) s += wacc[i];
        out[n*NT + t] = s / (float)RR;
    }
    __syncthreads();

    for (int idx = tid; idx < RR*RR; idx += 256){
        int r = idx / RR, c = idx - r*RR;
        sGH[r*49 + c] = g_H[(size_t)n*RR*RR + idx];
    }
    __syncthreads();

    // ---- t2i ----
    float accT = 0.f;
    for (int l = warp; l < LW; l += 8){
        int r0 = lane;
        bool h1 = lane < 16;
        int r1 = lane + 32;
        float y0 = sS[r0*65 + l] / rownorm[r0] * LAM;
        float y1 = h1 ? sS[r1*65 + l] / rownorm[r1] * LAM : -1e30f;
        float mx = wmax(fmaxf(y0, y1));
        float e0 = expf(y0 - mx);
        float e1 = h1 ? expf(y1 - mx) : 0.f;
        float sE = wsum(e0 + e1);
        float a0 = e0 / sE, a1 = e1 / sE;
        float sA = wsum(a0 + a1);
        float ta0 = (a0 * (float)RR - sA > 0.f) ? a0 : 0.f;
        float ta1 = (a1 * (float)RR - sA > 0.f) ? a1 : 0.f;
        float sT = wsum(ta0 + ta1);
        float dn = sT > 0.f ? sT : 1.f;
        float f0 = ta0 / dn, f1 = ta1 / dn;
        float num = f0 * sCt[l*49 + r0] + (h1 ? f1 * sCt[l*49 + r1] : 0.f);
        num = wsum(num);
        float qd = 0.f;
        for (int rp = 0; rp < RR; rp++){
            float arp = (rp < 32) ? __shfl_sync(0xffffffffu, f0, rp)
                                  : __shfl_sync(0xffffffffu, f1, rp - 32);
            float term = f0 * sGH[r0*49 + rp];
            if (h1) term += f1 * sGH[r1*49 + rp];
            qd += arp * term;
        }
        qd = wsum(qd);
        float wn = sqrtf(fmaxf(qd, 0.f));
        float inv = 1.f / (wn + EPSV);
        float xw = num * inv, whn = wn * inv;
        float den = fmaxf(g_ntv[t*LW + l] * whn, EPSV);
        float c2 = xw / den;
        if (l < len) accT += c2;
    }
    if (lane == 0) wacc[warp] = accT;
    __syncthreads();
    if (tid == 0){
        float s = 0.f;
        for (int i = 0; i < 8; i++) s += wacc[i];
        out[NI*NT + n*NT + t] = s / lenf;
    }
}

// ---------------- launch ----------------
extern "C" void kernel_launch(void* const* d_in, const int* in_sizes, int n_in,
                              void* d_out, int out_size){
    (void)in_sizes; (void)n_in; (void)out_size;
    const float* img_q = (const float*)d_in[0];
    const float* img_v = (const float*)d_in[1];
    const float* txt_k = (const float*)d_in[2];
    const float* txt_v = (const float*)d_in[3];
    const int*   tlen  = (const int*)d_in[4];
    float* out = (float*)d_out;

    void *pS, *pC, *pG, *pH;
    void *pqh, *pql, *pkh, *pkl, *pih, *pvh;
    cudaGetSymbolAddress(&pS, g_S);
    cudaGetSymbolAddress(&pC, g_C);
    cudaGetSymbolAddress(&pG, g_G);
    cudaGetSymbolAddress(&pH, g_H);
    cudaGetSymbolAddress(&pqh, g_qn_h);
    cudaGetSymbolAddress(&pql, g_qn_l);
    cudaGetSymbolAddress(&pkh, g_tk_h);
    cudaGetSymbolAddress(&pkl, g_tk_l);
    cudaGetSymbolAddress(&pih, g_iv_h);
    cudaGetSymbolAddress(&pvh, g_tv_h);

    cudaFuncSetAttribute(gemm_f16x3, cudaFuncAttributeMaxDynamicSharedMemorySize, SMEM3);
    cudaFuncSetAttribute(gemm_f16x1, cudaFuncAttributeMaxDynamicSharedMemorySize, SMEM1);

    prep_img_kernel<<<MM, 256>>>(img_q, img_v);
    prep_txt_kernel<<<NN, 256>>>(txt_k, txt_v, tlen);
    gram_kernel<RR><<<NI, 256>>>(img_v, (float*)pH);
    gram_kernel<LW><<<NT, 256>>>(txt_v, (float*)pG);

    dim3 gg(NN/128, MM/128);   // 64 x 48
    gemm_f16x3<<<gg, 256, SMEM3>>>((const __half*)pqh, (const __half*)pql,
                                   (const __half*)pkh, (const __half*)pkl, (float*)pS);
    gemm_f16x1<<<gg, 256, SMEM1>>>((const __half*)pih, (const __half*)pvh, (float*)pC);

    dim3 ge(NT, NI);           // x = t, y = n
    epilogue_kernel<<<ge, 256>>>(tlen, out);
}